// round 1
// baseline (speedup 1.0000x reference)
#include <cuda_runtime.h>

// EnhancedLesionPenaltyLoss: pred (16,1,128,128,128) fp32 -> scalar loss.
// Pass 1: one block per (batch, z-slice) computes 8 partial stats.
// Pass 2: one block, one warp per batch, reduces 128 slice-partials and
//         evaluates the loss formula in double; thread 0 averages batches.

namespace {
constexpr int NB     = 16;        // batches
constexpr int NZ     = 128;       // z slices
constexpr int SLICE4 = 4096;      // float4 per slice (128*128/4)
constexpr int SLICE  = 16384;     // floats per slice
constexpr long long VOL = 2097152; // 128^3
constexpr int NACC   = 8;         // cmin, cmax, max, sdw, sdh, sdd, s1, s2
}

__device__ float g_part[NB * NZ * NACC];

__device__ __forceinline__ float wsum(float v) {
#pragma unroll
    for (int o = 16; o; o >>= 1) v += __shfl_xor_sync(0xffffffffu, v, o);
    return v;
}
__device__ __forceinline__ float wmax(float v) {
#pragma unroll
    for (int o = 16; o; o >>= 1) v = fmaxf(v, __shfl_xor_sync(0xffffffffu, v, o));
    return v;
}

__global__ __launch_bounds__(256)
void lesion_pass1(const float* __restrict__ pred) {
    const int bid = blockIdx.x;
    const int b = bid >> 7;
    const int z = bid & 127;
    const float* __restrict__ sb = pred + (long long)b * VOL + (long long)z * SLICE;
    const float4* __restrict__ p  = reinterpret_cast<const float4*>(sb);
    const float4* __restrict__ pn = reinterpret_cast<const float4*>(sb + SLICE);
    const bool hasz = (z < 127);

    float cmin = 0.f, cmax = 0.f, mx = 0.f;
    float sdw = 0.f, sdh = 0.f, sdd = 0.f, s1 = 0.f, s2 = 0.f;

    for (int o = threadIdx.x; o < SLICE4; o += 256) {
        const float4 v = p[o];
        const int col4 = o & 31;   // float4 column within row (0..31)
        const int row  = o >> 5;   // row within slice (0..127)

        // w-direction |diffs| (3 intra-vector + 1 cross when not last vec of row)
        sdw += fabsf(v.y - v.x);
        sdw += fabsf(v.z - v.y);
        sdw += fabsf(v.w - v.z);
        if (col4 != 31) sdw += fabsf(sb[o * 4 + 4] - v.w);

        // h-direction (row+1 in same slice; L1-resident)
        if (row != 127) {
            const float4 h = p[o + 32];
            sdh += fabsf(h.x - v.x);
            sdh += fabsf(h.y - v.y);
            sdh += fabsf(h.z - v.z);
            sdh += fabsf(h.w - v.w);
        }
        // d-direction (next z slice; L2-resident thanks to adjacent blocks)
        if (hasz) {
            const float4 d = pn[o];
            sdd += fabsf(d.x - v.x);
            sdd += fabsf(d.y - v.y);
            sdd += fabsf(d.z - v.z);
            sdd += fabsf(d.w - v.w);
        }

        const float xs[4] = {v.x, v.y, v.z, v.w};
#pragma unroll
        for (int k = 0; k < 4; ++k) {
            const float x = xs[k];
            const float msk = (x > 0.01f) ? 1.f : 0.f;
            cmin += msk;
            const float xm = x * msk;
            s1 += xm;
            s2 = fmaf(x, xm, s2);
            if (x > 0.5f) cmax += 1.f;
            mx = fmaxf(mx, x);
        }
    }

    float acc[NACC] = {cmin, cmax, mx, sdw, sdh, sdd, s1, s2};
    __shared__ float red[8][NACC];
    const int lane = threadIdx.x & 31;
    const int wid  = threadIdx.x >> 5;
#pragma unroll
    for (int k = 0; k < NACC; ++k)
        acc[k] = (k == 2) ? wmax(acc[k]) : wsum(acc[k]);
    if (lane == 0) {
#pragma unroll
        for (int k = 0; k < NACC; ++k) red[wid][k] = acc[k];
    }
    __syncthreads();
    if (threadIdx.x < NACC) {
        const int k = threadIdx.x;
        float r = red[0][k];
#pragma unroll
        for (int w = 1; w < 8; ++w)
            r = (k == 2) ? fmaxf(r, red[w][k]) : (r + red[w][k]);
        g_part[bid * NACC + k] = r;
    }
}

__global__ __launch_bounds__(512)
void lesion_pass2(float* __restrict__ out) {
    const int tid  = threadIdx.x;
    const int bw   = tid >> 5;   // batch handled by this warp
    const int lane = tid & 31;
    __shared__ double lsh[NB];

    double a0 = 0, a1 = 0, a3 = 0, a4 = 0, a5 = 0, a6 = 0, a7 = 0;
    float mxl = 0.f;
    for (int s = lane; s < NZ; s += 32) {
        const float* pp = &g_part[(bw * NZ + s) * NACC];
        a0 += (double)pp[0];
        a1 += (double)pp[1];
        mxl = fmaxf(mxl, pp[2]);
        a3 += (double)pp[3];
        a4 += (double)pp[4];
        a5 += (double)pp[5];
        a6 += (double)pp[6];
        a7 += (double)pp[7];
    }
#pragma unroll
    for (int o = 16; o; o >>= 1) {
        a0 += __shfl_xor_sync(0xffffffffu, a0, o);
        a1 += __shfl_xor_sync(0xffffffffu, a1, o);
        a3 += __shfl_xor_sync(0xffffffffu, a3, o);
        a4 += __shfl_xor_sync(0xffffffffu, a4, o);
        a5 += __shfl_xor_sync(0xffffffffu, a5, o);
        a6 += __shfl_xor_sync(0xffffffffu, a6, o);
        a7 += __shfl_xor_sync(0xffffffffu, a7, o);
        mxl = fmaxf(mxl, __shfl_xor_sync(0xffffffffu, mxl, o));
    }
    if (lane == 0) {
        const double cnt = a0, chigh = a1;
        const double sdw = a3, sdh = a4, sdd = a5, S1 = a6, S2 = a7;
        const double N  = 2097152.0;       // 128^3
        const double ND = 2080768.0;       // 127*128*128

        const double act = cnt / N;
        double loss = fmax(0.005 - act, 0.0) * 15.0;

        const double high = chigh / N;
        loss += fmax(high - 0.03, 0.0) * 5.0;

        const double avg_grad = (sdd + sdh + sdw) / (3.0 * ND);
        if (mxl > 0.3f) loss += fmin(avg_grad, 1.0) * 5.0;

        const double cnt_safe = fmax(cnt, 1.0);
        const double m  = S1 / cnt_safe;
        const double sq = S2 - 2.0 * m * S1 + m * m * cnt;
        const bool gate = (act > 0.001) && (cnt > 1.0);
        const double var = gate ? sq / fmax(cnt - 1.0, 1.0) : 1.0;
        const double rel_std = sqrt(var) / (m + 1e-6);
        const double pen = exp(-5.0 * rel_std);
        loss += (gate ? pen : 0.0) * 7.0;

        lsh[bw] = loss;
    }
    __syncthreads();
    if (tid == 0) {
        double t = 0.0;
        for (int i = 0; i < NB; ++i) t += lsh[i];
        out[0] = (float)(t / 16.0);
    }
}

extern "C" void kernel_launch(void* const* d_in, const int* in_sizes, int n_in,
                              void* d_out, int out_size) {
    (void)in_sizes; (void)n_in; (void)out_size;
    const float* pred = (const float*)d_in[0];
    float* out = (float*)d_out;
    lesion_pass1<<<NB * NZ, 256>>>(pred);
    lesion_pass2<<<1, 512>>>(out);
}